// round 8
// baseline (speedup 1.0000x reference)
#include <cuda_runtime.h>
#include <cuda_bf16.h>
#include <cstdint>

#define B_    512
#define H_    1024
#define LDG   4352
#define NE    4096
#define ND    4352
#define KBE   2304      // Benc2 physical cols: Whi|Wlo|Wi_hi(128)|Wi_lo(128)
#define KBD   2176      // Bdec2 physical cols: Whi|Wlo|Wi_hi(64)|Wi_lo(64)
#define KTE   3456      // logical K enc
#define KTD   3264      // logical K dec

// ----------------------- device scratch (no allocs) ------------------------
__device__ __nv_bfloat16 g_Benc2[(size_t)NE * KBE];          // 18.9 MB
__device__ __nv_bfloat16 g_Bdec2[(size_t)ND * KBD];          // 18.9 MB
__device__ __nv_bfloat16 g_xenc2[(size_t)128 * B_ * 256];    // 33.5 MB
__device__ __nv_bfloat16 g_ftp2[(size_t)32 * B_ * 128];      // 4.2 MB
__device__ __nv_bfloat16 g_hP2[(size_t)B_ * 2048];           // hi|lo
__device__ float         g_h[(size_t)B_ * H_];
__device__ float         g_G[(size_t)B_ * LDG];
__device__ float         g_Wc[(size_t)3072 * H_];
__device__ float         g_wob[3072];

__device__ __forceinline__ __nv_bfloat16 split_val(float w, bool lo) {
    __nv_bfloat16 hi = __float2bfloat16(w);
    if (!lo) return hi;
    return __float2bfloat16(w - __bfloat162float(hi));
}

// ------------------------------ precompute ---------------------------------
__global__ void k_wc(const float* __restrict__ Wi, const float* __restrict__ Wd) {
    int idx = blockIdx.x * 256 + threadIdx.x;          // exact 3072*1024
    int n = idx >> 10, k = idx & 1023;
    const float* wrow = Wi + n * 128 + 64;
    float s = 0.f;
#pragma unroll 8
    for (int o = 0; o < 64; o++) s += wrow[o] * Wd[o * 1024 + k];
    g_Wc[idx] = s;
}

__global__ void k_wob(const float* __restrict__ Wi, const float* __restrict__ bd) {
    int n = blockIdx.x * 256 + threadIdx.x;
    if (n >= 3072) return;
    float s = 0.f;
#pragma unroll 8
    for (int o = 0; o < 64; o++) s += Wi[n * 128 + 64 + o] * bd[o];
    g_wob[n] = s;
}

// Benc2 rows: [0,2048)=r,z ; [2048,3072)=n_h ; [3072,4096)=n_i (Wi rows p-1024)
// cols: [0,1024) W-hi | [1024,2048) W-lo | [2048,2176) Wi-hi | [2176,2304) Wi-lo
__global__ void build_benc2(const float* __restrict__ Wi, const float* __restrict__ Wh) {
    size_t idx = (size_t)blockIdx.x * 256 + threadIdx.x;   // exact NE*KBE
    int p = (int)(idx / KBE);
    int c = (int)(idx - (size_t)p * KBE);
    float w = 0.f; bool lo = false;
    if (c < 2048) {
        int cc = c & 1023; lo = (c >= 1024);
        if (p < 3072) w = Wh[(size_t)p * 1024 + cc];
    } else {
        int q = c - 2048; lo = (q >= 128); q &= 127;
        if (p < 2048)       w = Wi[p * 128 + q];
        else if (p >= 3072) w = Wi[(p - 1024) * 128 + q];
    }
    g_Benc2[idx] = split_val(w, lo);
}

// Bdec2 rows: [0,2048)=r,z (Wh+Wc) ; [2048,3072)=n_h (Wh) ; [3072,4096)=n_i (Wc)
//             [4096,4160)=Wd ; rest 0.
// cols: [0,1024) W-hi | [1024,2048) W-lo | [2048,2112) Wi-hi | [2112,2176) Wi-lo
__global__ void build_bdec2(const float* __restrict__ Wi, const float* __restrict__ Wh,
                            const float* __restrict__ Wd) {
    size_t idx = (size_t)blockIdx.x * 256 + threadIdx.x;   // exact ND*KBD
    int p = (int)(idx / KBD);
    int c = (int)(idx - (size_t)p * KBD);
    float w = 0.f; bool lo = false;
    if (c < 2048) {
        int cc = c & 1023; lo = (c >= 1024);
        if (p < 2048)      w = Wh[(size_t)p * 1024 + cc] + g_Wc[(size_t)p * 1024 + cc];
        else if (p < 3072) w = Wh[(size_t)p * 1024 + cc];
        else if (p < 4096) w = g_Wc[(size_t)(p - 1024) * 1024 + cc];
        else if (p < 4160) w = Wd[(size_t)(p - 4096) * 1024 + cc];
    } else {
        int q = c - 2048; lo = (q >= 64); q &= 63;
        if (p < 2048)                      w = Wi[p * 128 + q];
        else if (p >= 3072 && p < 4096)    w = Wi[(p - 1024) * 128 + q];
    }
    g_Bdec2[idx] = split_val(w, lo);
}

// xenc2[t][m][c]: c<128 hi of x, c>=128 lo ; x = [prior_t | labels_t]
__global__ void k_xenc2(const float* __restrict__ feats, const float* __restrict__ labels) {
    size_t idx = (size_t)blockIdx.x * 256 + threadIdx.x;   // exact 128*B_*256
    int t = (int)(idx / ((size_t)B_ * 256));
    int rem = (int)(idx - (size_t)t * B_ * 256);
    int m = rem >> 8;
    int c = rem & 255;
    int kk = c & 127;
    float v = (kk < 64) ? feats[((size_t)m * 159 + t) * 64 + kk]
                        : labels[((size_t)m * 128 + t) * 64 + (kk - 64)];
    g_xenc2[idx] = split_val(v, c >= 128);
}

// ftp2[j][m][c]: c<64 hi, c>=64 lo ; slot 31 zero
__global__ void k_ftp2(const float* __restrict__ feats) {
    size_t idx = (size_t)blockIdx.x * 256 + threadIdx.x;   // exact 32*B_*128
    int j = (int)(idx / ((size_t)B_ * 128));
    int rem = (int)(idx - (size_t)j * B_ * 128);
    int m = rem >> 7;
    int c = rem & 127;
    float v = (j == 31) ? 0.f : feats[((size_t)m * 159 + 128 + j) * 64 + (c & 63)];
    g_ftp2[idx] = split_val(v, c >= 64);
}

__global__ void init_h() {
    int idx = blockIdx.x * 256 + threadIdx.x;              // exact B_*2048
    g_hP2[idx] = __float2bfloat16(0.f);
    if (idx < B_ * H_) g_h[idx] = 0.f;
}

// --------------------------- mma helpers -----------------------------------
__device__ __forceinline__ void ldsm4(unsigned& r0, unsigned& r1, unsigned& r2,
                                      unsigned& r3, const void* p) {
    unsigned a = (unsigned)__cvta_generic_to_shared(p);
    asm volatile("ldmatrix.sync.aligned.m8n8.x4.shared.b16 {%0,%1,%2,%3},[%4];"
                 : "=r"(r0), "=r"(r1), "=r"(r2), "=r"(r3) : "r"(a));
}

__device__ __forceinline__ void mma16816(float* c, const unsigned* a,
                                         unsigned b0, unsigned b1) {
    asm volatile(
        "mma.sync.aligned.m16n8k16.row.col.f32.bf16.bf16.f32 "
        "{%0,%1,%2,%3},{%4,%5,%6,%7},{%8,%9},{%0,%1,%2,%3};"
        : "+f"(c[0]), "+f"(c[1]), "+f"(c[2]), "+f"(c[3])
        : "r"(a[0]), "r"(a[1]), "r"(a[2]), "r"(a[3]), "r"(b0), "r"(b1));
}

__device__ __forceinline__ void cpa16(uint32_t dst, const void* src) {
    asm volatile("cp.async.cg.shared.global [%0], [%1], 16;" :: "r"(dst), "l"(src));
}
#define CP_COMMIT() asm volatile("cp.async.commit_group;" ::: "memory")
#define CP_WAIT1()  asm volatile("cp.async.wait_group 1;" ::: "memory")
#define CP_WAIT0()  asm volatile("cp.async.wait_group 0;" ::: "memory")

// ------------------------------- GEMM --------------------------------------
// 128x128 tile, KC=32 chunks, 3-stage cp.async ring, 2 CTAs/SM.
// Stage layout: A 128 rows x 40 bf16 (80B stride), B same; 20480B/stage.
#define KC     32
#define STGB   20480
#define SMEMD  (3 * STGB)

__global__ __launch_bounds__(256, 2)
void gemm2(int mode, int step) {
    extern __shared__ char dsm[];
    const int tid = threadIdx.x;
    const int lane = tid & 31, wid = tid >> 5;
    const int ntile = blockIdx.x;
    const int n0 = ntile * 128, m0 = blockIdx.y * 128;
    const int region = ntile >> 3;

    int kbeg, kend, KB;
    const __nv_bfloat16 *Bmat, *A2;
    int lda2;
    if (mode == 0) {
        kbeg = (region == 3) ? 3072 : 0;
        kend = (region == 2) ? 3072 : KTE;
        KB = KBE;
        Bmat = g_Benc2; A2 = g_xenc2 + (size_t)step * B_ * 256; lda2 = 256;
    } else {
        kbeg = 0;
        kend = (region == 2 || region >= 4) ? 3072 : KTD;
        KB = KBD;
        Bmat = g_Bdec2; A2 = g_ftp2 + (size_t)step * B_ * 128; lda2 = 128;
    }
    const int nch = (kend - kbeg) >> 5;

    const uint32_t sb = (unsigned)__cvta_generic_to_shared(dsm);

    auto FILL = [&](int f) {
        int kb = kbeg + f * KC;
        uint32_t base = sb + (f % 3) * STGB;
        // A source map (logical kb -> physical)
        const __nv_bfloat16* asrc; int lda, kc;
        if (kb < 2048)      { asrc = g_hP2; lda = 2048; kc = kb; }
        else if (kb < 3072) { asrc = g_hP2; lda = 2048; kc = kb - 2048; }
        else {
            asrc = A2; lda = lda2;
            if (mode == 0) kc = (kb < 3328) ? kb - 3072 : kb - 3328;
            else           kc = (kb < 3200) ? kb - 3072 : kb - 3200;
        }
        // B source map
        int bc;
        if (mode == 0) bc = (kb < 1024) ? kb : ((kb < 3200) ? kb - 1024 : kb - 1152);
        else           bc = (kb < 1024) ? kb : ((kb < 3136) ? kb - 1024 : kb - 1088);
#pragma unroll
        for (int it = 0; it < 4; it++) {
            int ch = tid + it * 256;         // 0..1023
            int isB = ch >= 512;
            int g = isB ? ch - 512 : ch;
            int row = g >> 2, seg = g & 3;
            const char* src;
            uint32_t dst = base + (isB ? 10240 : 0) + row * 80 + seg * 16;
            if (!isB)
                src = (const char*)(asrc + (size_t)(m0 + row) * lda + kc) + seg * 16;
            else
                src = (const char*)(Bmat + (size_t)(n0 + row) * KB + bc) + seg * 16;
            cpa16(dst, src);
        }
        CP_COMMIT();
    };

    const int wm = (wid & 3) * 32, wn = (wid >> 2) * 64;
    const int grp = lane >> 2, tig = lane & 3;

    float acc[2][8][4];
#pragma unroll
    for (int i = 0; i < 2; i++)
#pragma unroll
        for (int j = 0; j < 8; j++)
#pragma unroll
            for (int q = 0; q < 4; q++) acc[i][j][q] = 0.f;

    FILL(0); FILL(1);

    for (int i = 0; i < nch; i++) {
        if (i + 1 < nch) CP_WAIT1(); else CP_WAIT0();
        __syncthreads();
        __nv_bfloat16* As = (__nv_bfloat16*)(dsm + (i % 3) * STGB);
        __nv_bfloat16* Bs = As + 5120;

#pragma unroll
        for (int kh = 0; kh < 32; kh += 16) {
            unsigned a[2][4], b[4][4];
#pragma unroll
            for (int mi = 0; mi < 2; mi++)
                ldsm4(a[mi][0], a[mi][1], a[mi][2], a[mi][3],
                      As + (wm + mi * 16 + (lane & 15)) * 40 + kh + (lane >> 4) * 8);
#pragma unroll
            for (int np = 0; np < 4; np++)
                ldsm4(b[np][0], b[np][1], b[np][2], b[np][3],
                      Bs + (wn + np * 16 + (lane & 15)) * 40 + kh + (lane >> 4) * 8);
#pragma unroll
            for (int mi = 0; mi < 2; mi++)
#pragma unroll
                for (int nj = 0; nj < 8; nj++) {
                    int np = nj >> 1;
                    unsigned b0 = (nj & 1) ? b[np][1] : b[np][0];
                    unsigned b1 = (nj & 1) ? b[np][3] : b[np][2];
                    mma16816(acc[mi][nj], a[mi], b0, b1);
                }
        }

        int f = i + 2;
        if (f < nch) FILL(f);
    }

#pragma unroll
    for (int mi = 0; mi < 2; mi++)
#pragma unroll
        for (int nj = 0; nj < 8; nj++) {
            int row = m0 + wm + mi * 16 + grp;
            int col = n0 + wn + nj * 8 + tig * 2;
            *(float2*)&g_G[(size_t)row * LDG + col] =
                make_float2(acc[mi][nj][0], acc[mi][nj][1]);
            *(float2*)&g_G[(size_t)(row + 8) * LDG + col] =
                make_float2(acc[mi][nj][2], acc[mi][nj][3]);
        }
}

// ------------------------------ pointwise ----------------------------------
__global__ void pointwise(int mode, const float* __restrict__ bi,
                          const float* __restrict__ bh) {
    int idx = blockIdx.x * 256 + threadIdx.x;     // exact 512*1024
    int m = idx >> 10, n = idx & 1023;
    const float* Gr = g_G + (size_t)m * LDG;
    float wr = mode ? g_wob[n] : 0.f;
    float wz = mode ? g_wob[1024 + n] : 0.f;
    float wn_ = mode ? g_wob[2048 + n] : 0.f;
    float r = Gr[n] + bi[n] + bh[n] + wr;
    float z = Gr[1024 + n] + bi[1024 + n] + bh[1024 + n] + wz;
    float ghn = Gr[2048 + n] + bh[2048 + n];
    float gin = Gr[3072 + n] + bi[2048 + n] + wn_;
    r = 1.f / (1.f + __expf(-r));
    z = 1.f / (1.f + __expf(-z));
    float nn = tanhf(gin + r * ghn);
    float ho = g_h[idx];
    float h = (1.f - z) * nn + z * ho;
    g_h[idx] = h;
    __nv_bfloat16 hi = __float2bfloat16(h);
    __nv_bfloat16 lo = __float2bfloat16(h - __bfloat162float(hi));
    g_hP2[(size_t)m * 2048 + n] = hi;
    g_hP2[(size_t)m * 2048 + 1024 + n] = lo;
}

__global__ void psout(float* __restrict__ out, const float* __restrict__ bd) {
    int idx = blockIdx.x * 256 + threadIdx.x;     // exact 512*64
    int m = idx >> 6, o = idx & 63;
    out[idx] = g_G[(size_t)m * LDG + 4096 + o] + bd[o];
}

// ------------------------------- launch ------------------------------------
extern "C" void kernel_launch(void* const* d_in, const int* in_sizes, int n_in,
                              void* d_out, int out_size) {
    const float* feats  = (const float*)d_in[0];
    const float* labels = (const float*)d_in[1];
    const float* Wi     = (const float*)d_in[2];
    const float* Wh     = (const float*)d_in[3];
    const float* bi     = (const float*)d_in[4];
    const float* bh     = (const float*)d_in[5];
    const float* Wd     = (const float*)d_in[6];
    const float* bd     = (const float*)d_in[7];
    float* out = (float*)d_out;

    cudaFuncSetAttribute(gemm2, cudaFuncAttributeMaxDynamicSharedMemorySize, SMEMD);

    k_wc<<<12288, 256>>>(Wi, Wd);
    k_wob<<<12, 256>>>(Wi, bd);
    build_benc2<<<(int)(((size_t)NE * KBE) / 256), 256>>>(Wi, Wh);
    build_bdec2<<<(int)(((size_t)ND * KBD) / 256), 256>>>(Wi, Wh, Wd);
    k_xenc2<<<(int)(((size_t)128 * B_ * 256) / 256), 256>>>(feats, labels);
    k_ftp2<<<(int)(((size_t)32 * B_ * 128) / 256), 256>>>(feats);
    init_h<<<(B_ * 2048) / 256, 256>>>();

    for (int t = 0; t < 128; t++) {
        gemm2<<<dim3(32, 4), 256, SMEMD>>>(0, t);
        pointwise<<<2048, 256>>>(0, bi, bh);
    }
    for (int j = 0; j < 32; j++) {
        gemm2<<<dim3(34, 4), 256, SMEMD>>>(1, j);
        psout<<<128, 256>>>(out + (size_t)j * B_ * 64, bd);
        if (j < 31) pointwise<<<2048, 256>>>(1, bi, bh);
    }
}

// round 9
// speedup vs baseline: 1.2041x; 1.2041x over previous
#include <cuda_runtime.h>
#include <cuda_bf16.h>
#include <cstdint>

#define B_    512
#define H_    1024
#define LDG   4352
#define NE    4096
#define ND    4352
#define KBE   2304      // Benc2 physical cols: Whi|Wlo|Wi_hi(128)|Wi_lo(128)
#define KBD   2176      // Bdec2 physical cols: Whi|Wlo|Wi_hi(64)|Wi_lo(64)
#define KTE   3456      // logical K enc
#define KTD   3264      // logical K dec

// ----------------------- device scratch (no allocs) ------------------------
__device__ __nv_bfloat16 g_Benc2[(size_t)NE * KBE];
__device__ __nv_bfloat16 g_Bdec2[(size_t)ND * KBD];
__device__ __nv_bfloat16 g_xenc2[(size_t)128 * B_ * 256];
__device__ __nv_bfloat16 g_ftp2[(size_t)32 * B_ * 128];
__device__ __nv_bfloat16 g_hP2[(size_t)B_ * 2048];           // hi|lo
__device__ float         g_h[(size_t)B_ * H_];
__device__ float         g_G[(size_t)B_ * LDG];
__device__ float         g_Wc[(size_t)3072 * H_];
__device__ float         g_wob[3072];

__device__ __forceinline__ __nv_bfloat16 split_val(float w, bool lo) {
    __nv_bfloat16 hi = __float2bfloat16(w);
    if (!lo) return hi;
    return __float2bfloat16(w - __bfloat162float(hi));
}

// ------------------------------ precompute ---------------------------------
__global__ void k_wc(const float* __restrict__ Wi, const float* __restrict__ Wd) {
    int idx = blockIdx.x * 256 + threadIdx.x;          // exact 3072*1024
    int n = idx >> 10, k = idx & 1023;
    const float* wrow = Wi + n * 128 + 64;
    float s = 0.f;
#pragma unroll 8
    for (int o = 0; o < 64; o++) s += wrow[o] * Wd[o * 1024 + k];
    g_Wc[idx] = s;
}

__global__ void k_wob(const float* __restrict__ Wi, const float* __restrict__ bd) {
    int n = blockIdx.x * 256 + threadIdx.x;
    if (n >= 3072) return;
    float s = 0.f;
#pragma unroll 8
    for (int o = 0; o < 64; o++) s += Wi[n * 128 + 64 + o] * bd[o];
    g_wob[n] = s;
}

// Benc2 rows: [0,2048)=r,z ; [2048,3072)=n_h ; [3072,4096)=n_i (Wi rows p-1024)
// cols: [0,1024) W-hi | [1024,2048) W-lo | [2048,2176) Wi-hi | [2176,2304) Wi-lo
__global__ void build_benc2(const float* __restrict__ Wi, const float* __restrict__ Wh) {
    size_t idx = (size_t)blockIdx.x * 256 + threadIdx.x;   // exact NE*KBE
    int p = (int)(idx / KBE);
    int c = (int)(idx - (size_t)p * KBE);
    float w = 0.f; bool lo = false;
    if (c < 2048) {
        int cc = c & 1023; lo = (c >= 1024);
        if (p < 3072) w = Wh[(size_t)p * 1024 + cc];
    } else {
        int q = c - 2048; lo = (q >= 128); q &= 127;
        if (p < 2048)       w = Wi[p * 128 + q];
        else if (p >= 3072) w = Wi[(p - 1024) * 128 + q];
    }
    g_Benc2[idx] = split_val(w, lo);
}

// Bdec2 rows: [0,2048)=r,z (Wh+Wc) ; [2048,3072)=n_h (Wh) ; [3072,4096)=n_i (Wc)
//             [4096,4160)=Wd ; rest 0.
// cols: [0,1024) W-hi | [1024,2048) W-lo | [2048,2112) Wi-hi | [2112,2176) Wi-lo
__global__ void build_bdec2(const float* __restrict__ Wi, const float* __restrict__ Wh,
                            const float* __restrict__ Wd) {
    size_t idx = (size_t)blockIdx.x * 256 + threadIdx.x;   // exact ND*KBD
    int p = (int)(idx / KBD);
    int c = (int)(idx - (size_t)p * KBD);
    float w = 0.f; bool lo = false;
    if (c < 2048) {
        int cc = c & 1023; lo = (c >= 1024);
        if (p < 2048)      w = Wh[(size_t)p * 1024 + cc] + g_Wc[(size_t)p * 1024 + cc];
        else if (p < 3072) w = Wh[(size_t)p * 1024 + cc];
        else if (p < 4096) w = g_Wc[(size_t)(p - 1024) * 1024 + cc];
        else if (p < 4160) w = Wd[(size_t)(p - 4096) * 1024 + cc];
    } else {
        int q = c - 2048; lo = (q >= 64); q &= 63;
        if (p < 2048)                      w = Wi[p * 128 + q];
        else if (p >= 3072 && p < 4096)    w = Wi[(p - 1024) * 128 + q];
    }
    g_Bdec2[idx] = split_val(w, lo);
}

// xenc2[t][m][c]: c<128 hi of x, c>=128 lo ; x = [prior_t | labels_t]
__global__ void k_xenc2(const float* __restrict__ feats, const float* __restrict__ labels) {
    size_t idx = (size_t)blockIdx.x * 256 + threadIdx.x;   // exact 128*B_*256
    int t = (int)(idx / ((size_t)B_ * 256));
    int rem = (int)(idx - (size_t)t * B_ * 256);
    int m = rem >> 8;
    int c = rem & 255;
    int kk = c & 127;
    float v = (kk < 64) ? feats[((size_t)m * 159 + t) * 64 + kk]
                        : labels[((size_t)m * 128 + t) * 64 + (kk - 64)];
    g_xenc2[idx] = split_val(v, c >= 128);
}

// ftp2[j][m][c]: c<64 hi, c>=64 lo ; slot 31 zero
__global__ void k_ftp2(const float* __restrict__ feats) {
    size_t idx = (size_t)blockIdx.x * 256 + threadIdx.x;   // exact 32*B_*128
    int j = (int)(idx / ((size_t)B_ * 128));
    int rem = (int)(idx - (size_t)j * B_ * 128);
    int m = rem >> 7;
    int c = rem & 127;
    float v = (j == 31) ? 0.f : feats[((size_t)m * 159 + 128 + j) * 64 + (c & 63)];
    g_ftp2[idx] = split_val(v, c >= 64);
}

__global__ void init_h() {
    int idx = blockIdx.x * 256 + threadIdx.x;              // exact B_*2048
    g_hP2[idx] = __float2bfloat16(0.f);
    if (idx < B_ * H_) g_h[idx] = 0.f;
}

// --------------------------- mma helpers -----------------------------------
__device__ __forceinline__ void ldsm4(unsigned& r0, unsigned& r1, unsigned& r2,
                                      unsigned& r3, const void* p) {
    unsigned a = (unsigned)__cvta_generic_to_shared(p);
    asm volatile("ldmatrix.sync.aligned.m8n8.x4.shared.b16 {%0,%1,%2,%3},[%4];"
                 : "=r"(r0), "=r"(r1), "=r"(r2), "=r"(r3) : "r"(a));
}

__device__ __forceinline__ void mma16816(float* c, const unsigned* a,
                                         unsigned b0, unsigned b1) {
    asm volatile(
        "mma.sync.aligned.m16n8k16.row.col.f32.bf16.bf16.f32 "
        "{%0,%1,%2,%3},{%4,%5,%6,%7},{%8,%9},{%0,%1,%2,%3};"
        : "+f"(c[0]), "+f"(c[1]), "+f"(c[2]), "+f"(c[3])
        : "r"(a[0]), "r"(a[1]), "r"(a[2]), "r"(a[3]), "r"(b0), "r"(b1));
}

__device__ __forceinline__ void cpa16(uint32_t dst, const void* src) {
    asm volatile("cp.async.cg.shared.global [%0], [%1], 16;" :: "r"(dst), "l"(src));
}
#define CP_COMMIT() asm volatile("cp.async.commit_group;" ::: "memory")
#define CP_WAIT2()  asm volatile("cp.async.wait_group 2;" ::: "memory")

// ------------------------------- GEMM --------------------------------------
// 128x128 tile, KC=64 chunks, 4-stage cp.async ring (depth-3 prefetch).
// Stage: A 128 rows x 72 bf16 (144B stride) + B same = 36864B.
#define KC     64
#define ROWB   144
#define STGB   36864
#define SMEMD  (4 * STGB)

__global__ __launch_bounds__(256)
void gemm2(int mode, int step) {
    extern __shared__ char dsm[];
    const int tid = threadIdx.x;
    const int lane = tid & 31, wid = tid >> 5;
    const int ntile = blockIdx.x;
    const int n0 = ntile * 128, m0 = blockIdx.y * 128;
    const int region = ntile >> 3;

    int kbeg, kend, KB;
    const __nv_bfloat16 *Bmat, *A2;
    int lda2;
    if (mode == 0) {
        kbeg = (region == 3) ? 3072 : 0;
        kend = (region == 2) ? 3072 : KTE;
        KB = KBE;
        Bmat = g_Benc2; A2 = g_xenc2 + (size_t)step * B_ * 256; lda2 = 256;
    } else {
        kbeg = 0;
        kend = (region == 2 || region >= 4) ? 3072 : KTD;
        KB = KBD;
        Bmat = g_Bdec2; A2 = g_ftp2 + (size_t)step * B_ * 128; lda2 = 128;
    }
    const int nch = (kend - kbeg) >> 6;

    const uint32_t sb = (unsigned)__cvta_generic_to_shared(dsm);

    auto FILL = [&](int f) {
        int kb = kbeg + f * KC;
        uint32_t base = sb + (f & 3) * STGB;
        // A source map (logical kb -> physical)
        const __nv_bfloat16* asrc; int lda, kc;
        if (kb < 2048)      { asrc = g_hP2; lda = 2048; kc = kb; }
        else if (kb < 3072) { asrc = g_hP2; lda = 2048; kc = kb - 2048; }
        else {
            asrc = A2; lda = lda2;
            if (mode == 0) kc = (kb < 3328) ? kb - 3072 : kb - 3328;
            else           kc = (kb < 3200) ? kb - 3072 : kb - 3200;
        }
        // B source map
        int bc;
        if (mode == 0) bc = (kb < 1024) ? kb : ((kb < 3200) ? kb - 1024 : kb - 1152);
        else           bc = (kb < 1024) ? kb : ((kb < 3136) ? kb - 1024 : kb - 1088);
#pragma unroll
        for (int it = 0; it < 8; it++) {
            int ch = tid + it * 256;         // 0..2047
            int isB = ch >= 1024;
            int g = ch & 1023;
            int row = g >> 3, seg = g & 7;
            const char* src;
            uint32_t dst = base + (isB ? (128 * ROWB) : 0) + row * ROWB + seg * 16;
            if (!isB)
                src = (const char*)(asrc + (size_t)(m0 + row) * lda + kc) + seg * 16;
            else
                src = (const char*)(Bmat + (size_t)(n0 + row) * KB + bc) + seg * 16;
            cpa16(dst, src);
        }
        CP_COMMIT();
    };

    const int wm = (wid & 3) * 32, wn = (wid >> 2) * 64;
    const int grp = lane >> 2, tig = lane & 3;

    float acc[2][8][4];
#pragma unroll
    for (int i = 0; i < 2; i++)
#pragma unroll
        for (int j = 0; j < 8; j++)
#pragma unroll
            for (int q = 0; q < 4; q++) acc[i][j][q] = 0.f;

    FILL(0); FILL(1); FILL(2);

    for (int i = 0; i < nch; i++) {
        CP_WAIT2();
        __syncthreads();
        __nv_bfloat16* As = (__nv_bfloat16*)(dsm + (i & 3) * STGB);
        __nv_bfloat16* Bs = As + 128 * 72;

#pragma unroll
        for (int kh = 0; kh < 64; kh += 16) {
            unsigned a[2][4], b[4][4];
#pragma unroll
            for (int mi = 0; mi < 2; mi++)
                ldsm4(a[mi][0], a[mi][1], a[mi][2], a[mi][3],
                      As + (wm + mi * 16 + (lane & 15)) * 72 + kh + (lane >> 4) * 8);
#pragma unroll
            for (int np = 0; np < 4; np++)
                ldsm4(b[np][0], b[np][1], b[np][2], b[np][3],
                      Bs + (wn + np * 16 + (lane & 15)) * 72 + kh + (lane >> 4) * 8);
#pragma unroll
            for (int mi = 0; mi < 2; mi++)
#pragma unroll
                for (int nj = 0; nj < 8; nj++) {
                    int np = nj >> 1;
                    unsigned b0 = (nj & 1) ? b[np][1] : b[np][0];
                    unsigned b1 = (nj & 1) ? b[np][3] : b[np][2];
                    mma16816(acc[mi][nj], a[mi], b0, b1);
                }
        }

        int f = i + 3;
        if (f < nch) FILL(f); else CP_COMMIT();
    }

#pragma unroll
    for (int mi = 0; mi < 2; mi++)
#pragma unroll
        for (int nj = 0; nj < 8; nj++) {
            int row = m0 + wm + mi * 16 + grp;
            int col = n0 + wn + nj * 8 + tig * 2;
            *(float2*)&g_G[(size_t)row * LDG + col] =
                make_float2(acc[mi][nj][0], acc[mi][nj][1]);
            *(float2*)&g_G[(size_t)(row + 8) * LDG + col] =
                make_float2(acc[mi][nj][2], acc[mi][nj][3]);
        }
}

// ------------------------------ pointwise ----------------------------------
// blocks [0,2048): gate math (skipped if !do_h). blocks [2048,2176): psout.
__global__ void pointwise(int mode, int do_h, const float* __restrict__ bi,
                          const float* __restrict__ bh, const float* __restrict__ bd,
                          float* __restrict__ out) {
    int blk = blockIdx.x;
    if (blk >= 2048) {
        int idx = (blk - 2048) * 256 + threadIdx.x;   // exact 512*64
        int m = idx >> 6, o = idx & 63;
        out[idx] = g_G[(size_t)m * LDG + 4096 + o] + bd[o];
        return;
    }
    if (!do_h) return;
    int idx = blk * 256 + threadIdx.x;                // exact 512*1024
    int m = idx >> 10, n = idx & 1023;
    const float* Gr = g_G + (size_t)m * LDG;
    float wr = mode ? g_wob[n] : 0.f;
    float wz = mode ? g_wob[1024 + n] : 0.f;
    float wn_ = mode ? g_wob[2048 + n] : 0.f;
    float r = Gr[n] + bi[n] + bh[n] + wr;
    float z = Gr[1024 + n] + bi[1024 + n] + bh[1024 + n] + wz;
    float ghn = Gr[2048 + n] + bh[2048 + n];
    float gin = Gr[3072 + n] + bi[2048 + n] + wn_;
    r = 1.f / (1.f + __expf(-r));
    z = 1.f / (1.f + __expf(-z));
    float nn = tanhf(gin + r * ghn);
    float ho = g_h[idx];
    float h = (1.f - z) * nn + z * ho;
    g_h[idx] = h;
    __nv_bfloat16 hi = __float2bfloat16(h);
    __nv_bfloat16 lo = __float2bfloat16(h - __bfloat162float(hi));
    g_hP2[(size_t)m * 2048 + n] = hi;
    g_hP2[(size_t)m * 2048 + 1024 + n] = lo;
}

// ------------------------------- launch ------------------------------------
extern "C" void kernel_launch(void* const* d_in, const int* in_sizes, int n_in,
                              void* d_out, int out_size) {
    const float* feats  = (const float*)d_in[0];
    const float* labels = (const float*)d_in[1];
    const float* Wi     = (const float*)d_in[2];
    const float* Wh     = (const float*)d_in[3];
    const float* bi     = (const float*)d_in[4];
    const float* bh     = (const float*)d_in[5];
    const float* Wd     = (const float*)d_in[6];
    const float* bd     = (const float*)d_in[7];
    float* out = (float*)d_out;

    cudaFuncSetAttribute(gemm2, cudaFuncAttributeMaxDynamicSharedMemorySize, SMEMD);

    k_wc<<<12288, 256>>>(Wi, Wd);
    k_wob<<<12, 256>>>(Wi, bd);
    build_benc2<<<(int)(((size_t)NE * KBE) / 256), 256>>>(Wi, Wh);
    build_bdec2<<<(int)(((size_t)ND * KBD) / 256), 256>>>(Wi, Wh, Wd);
    k_xenc2<<<(int)(((size_t)128 * B_ * 256) / 256), 256>>>(feats, labels);
    k_ftp2<<<(int)(((size_t)32 * B_ * 128) / 256), 256>>>(feats);
    init_h<<<(B_ * 2048) / 256, 256>>>();

    for (int t = 0; t < 128; t++) {
        gemm2<<<dim3(32, 4), 256, SMEMD>>>(0, t);
        pointwise<<<2048, 256>>>(0, 1, bi, bh, bd, out);
    }
    for (int j = 0; j < 32; j++) {
        gemm2<<<dim3(34, 4), 256, SMEMD>>>(1, j);
        pointwise<<<2176, 256>>>(1, (j < 31) ? 1 : 0, bi, bh, bd,
                                 out + (size_t)j * B_ * 64);
    }
}